// round 15
// baseline (speedup 1.0000x reference)
#include <cuda_runtime.h>
#include <cuda_fp16.h>
#include <cstdint>
#include <math.h>

// ---------------------------------------------------------------------------
// DotProductAttention (sm_103 plain -> mma.sync m16n8k16 fp16).
// R15: R14 + hoisted fragment loads (A for both k-slices upfront; 1-pass also
// hoists B) to lengthen contiguous HMMA bursts. Numerics bit-identical.
// ---------------------------------------------------------------------------

#define BATCH 4
#define SEQ   2048
#define MODEL 1024
#define MTOT  (BATCH * SEQ)   // 8192
#define PERSIST 296

__device__ uint32_t g_qAH[(size_t)MTOT * MODEL / 2];
__device__ uint32_t g_qAL[(size_t)MTOT * MODEL / 2];
__device__ uint32_t g_kAH[(size_t)MTOT * MODEL / 2];
__device__ uint32_t g_kAL[(size_t)MTOT * MODEL / 2];
__device__ uint32_t g_vAH[(size_t)MTOT * MODEL / 2];
__device__ uint32_t g_WqH[MODEL * MODEL / 2];
__device__ uint32_t g_WqL[MODEL * MODEL / 2];
__device__ uint32_t g_WkH[MODEL * MODEL / 2];
__device__ uint32_t g_WkL[MODEL * MODEL / 2];
__device__ uint32_t g_WvH[MODEL * MODEL / 2];
__device__ uint32_t g_QH[(size_t)MTOT * MODEL / 2];
__device__ uint32_t g_QL[(size_t)MTOT * MODEL / 2];
__device__ uint32_t g_KH[(size_t)MTOT * MODEL / 2];
__device__ uint32_t g_KL[(size_t)MTOT * MODEL / 2];
__device__ uint32_t g_Vh[(size_t)MTOT * MODEL / 2];
__device__ uint32_t g_VT[(size_t)BATCH * (MODEL / 8) * (SEQ / 16) * 64];
__device__ uint32_t g_P [(size_t)MTOT * (SEQ / 2)];
__device__ float    g_S [(size_t)BATCH * SEQ * SEQ];

__device__ __forceinline__ void f16_split2(float a, float b, uint32_t& hi, uint32_t& lo) {
    __half ha = __float2half_rn(a), hb = __float2half_rn(b);
    __half la = __float2half_rn(a - __half2float(ha));
    __half lb = __float2half_rn(b - __half2float(hb));
    hi = ((uint32_t)__half_as_ushort(hb) << 16) | (uint32_t)__half_as_ushort(ha);
    lo = ((uint32_t)__half_as_ushort(lb) << 16) | (uint32_t)__half_as_ushort(la);
}
__device__ __forceinline__ uint32_t f16_pack2(float a, float b) {
    __half ha = __float2half_rn(a), hb = __float2half_rn(b);
    return ((uint32_t)__half_as_ushort(hb) << 16) | (uint32_t)__half_as_ushort(ha);
}
__device__ __forceinline__ void mma_f16(float* c, const uint32_t* a, const uint32_t* b) {
    asm volatile(
        "mma.sync.aligned.m16n8k16.row.col.f32.f16.f16.f32 "
        "{%0,%1,%2,%3}, {%4,%5,%6,%7}, {%8,%9}, {%0,%1,%2,%3};"
        : "+f"(c[0]), "+f"(c[1]), "+f"(c[2]), "+f"(c[3])
        : "r"(a[0]), "r"(a[1]), "r"(a[2]), "r"(a[3]), "r"(b[0]), "r"(b[1]));
}
__device__ __forceinline__ void cp16(uint32_t s, const void* g) {
    asm volatile("cp.async.cg.shared.global [%0], [%1], 16;" :: "r"(s), "l"(g));
}
__device__ __forceinline__ void cp_commit() { asm volatile("cp.async.commit_group;" ::: "memory"); }
template <int N> __device__ __forceinline__ void cp_wait() {
    asm volatile("cp.async.wait_group %0;" :: "n"(N) : "memory");
}

// ========== shared GEMM core: BK=32, 3-stage ring, paired-B planes =========
template <int PASSES>
__device__ __forceinline__ void gemm_core(
    uint32_t* smBase, uint32_t sb0,
    const uint32_t* __restrict__ AH, const uint32_t* __restrict__ AL, int nktA,
    const uint32_t* __restrict__ BH, const uint32_t* __restrict__ BL, int nktB,
    int mtBase, int pBase, int nk32, float (&acc)[4][8][4])
{
    constexpr bool P3 = (PASSES == 3);
    constexpr int OFF_ALO = 2048;
    constexpr int OFF_B  = P3 ? 4096 : 2048;
    constexpr int OFF_BLO = OFF_B + 2048;
    constexpr int STG = P3 ? 8192 : 4096;

    const int tid = threadIdx.x, wid = tid >> 5, lane = tid & 31;
    const int warpM = wid & 1, warpN = wid >> 1;

    const uint32_t *pA[4], *pAl[4], *pB[4], *pBl[4];
    uint32_t dOff[4];
#pragma unroll
    for (int j = 0; j < 4; j++) {
        const int gi = tid + j * 128;
        const int ks = gi >> 8;
        const int blk = (gi >> 5) & 7;
        const int w = (gi & 31) * 4;
        dOff[j] = (uint32_t)(ks * 1024 + blk * 128 + w);
        pA[j] = AH + ((size_t)(mtBase + blk) * nktA + ks) * 128 + w;
        pB[j] = BH + ((size_t)(pBase + blk) * nktB + ks) * 128 + w;
        if (P3) {
            pAl[j] = AL + ((size_t)(mtBase + blk) * nktA + ks) * 128 + w;
            pBl[j] = BL + ((size_t)(pBase + blk) * nktB + ks) * 128 + w;
        }
    }

    auto issue = [&](int it, int stg) {
        const uint32_t s = sb0 + stg * (STG * 4);
        const size_t kadd = (size_t)it * 256;
#pragma unroll
        for (int j = 0; j < 4; j++) {
            cp16(s + dOff[j] * 4, pA[j] + kadd);
            if (P3) cp16(s + (OFF_ALO + dOff[j]) * 4, pAl[j] + kadd);
            cp16(s + (OFF_B + dOff[j]) * 4, pB[j] + kadd);
            if (P3) cp16(s + (OFF_BLO + dOff[j]) * 4, pBl[j] + kadd);
        }
        cp_commit();
    };

#pragma unroll
    for (int mt = 0; mt < 4; mt++)
#pragma unroll
        for (int nt = 0; nt < 8; nt++)
#pragma unroll
            for (int e = 0; e < 4; e++) acc[mt][nt][e] = 0.0f;

    __syncthreads();
    issue(0, 0);
    issue(1, 1);

    int slot = 0;
    for (int i = 0; i < nk32; i++) {
        if (i + 1 < nk32) cp_wait<1>();
        else              cp_wait<0>();
        __syncthreads();

        if (i + 2 < nk32) {
            int nslot = slot + 2;
            if (nslot >= 3) nslot -= 3;
            issue(i + 2, nslot);
        }

        const uint32_t* s = smBase + slot * STG;

        // hoist A fragments for BOTH k-slices (both passes' planes if P3)
        uint32_t aHi[2][4][4], aLo[2][4][4];
#pragma unroll
        for (int ks = 0; ks < 2; ks++) {
            const uint32_t* sl = s + ks * 1024;
#pragma unroll
            for (int mt = 0; mt < 4; mt++) {
                const uint32_t* ap = sl + (warpM * 4 + mt) * 128 + lane * 4;
                *(uint4*)aHi[ks][mt] = *(const uint4*)ap;
                if (P3) *(uint4*)aLo[ks][mt] = *(const uint4*)(ap + OFF_ALO);
            }
        }

        if (!P3) {
            // 1-pass: hoist B for both slices too, then one 128-HMMA burst
            uint32_t bHi[2][8][2];
#pragma unroll
            for (int ks = 0; ks < 2; ks++) {
                const uint32_t* sl = s + ks * 1024;
#pragma unroll
                for (int pp = 0; pp < 4; pp++) {
                    const uint32_t* bp = sl + OFF_B + (warpN * 4 + pp) * 128 + lane * 4;
                    const uint4 bh = *(const uint4*)bp;
                    bHi[ks][2 * pp][0] = bh.x; bHi[ks][2 * pp][1] = bh.y;
                    bHi[ks][2 * pp + 1][0] = bh.z; bHi[ks][2 * pp + 1][1] = bh.w;
                }
            }
#pragma unroll
            for (int ks = 0; ks < 2; ks++)
#pragma unroll
                for (int mt = 0; mt < 4; mt++)
#pragma unroll
                    for (int nt = 0; nt < 8; nt++)
                        mma_f16(acc[mt][nt], aHi[ks][mt], bHi[ks][nt]);
        } else {
#pragma unroll
            for (int ks = 0; ks < 2; ks++) {
                const uint32_t* sl = s + ks * 1024;
                uint32_t bHi[8][2], bLo[8][2];
#pragma unroll
                for (int pp = 0; pp < 4; pp++) {
                    const uint32_t* bp = sl + OFF_B + (warpN * 4 + pp) * 128 + lane * 4;
                    const uint4 bh = *(const uint4*)bp;
                    bHi[2 * pp][0] = bh.x; bHi[2 * pp][1] = bh.y;
                    bHi[2 * pp + 1][0] = bh.z; bHi[2 * pp + 1][1] = bh.w;
                    const uint4 bl = *(const uint4*)(bp + 2048);
                    bLo[2 * pp][0] = bl.x; bLo[2 * pp][1] = bl.y;
                    bLo[2 * pp + 1][0] = bl.z; bLo[2 * pp + 1][1] = bl.w;
                }
#pragma unroll
                for (int mt = 0; mt < 4; mt++)
#pragma unroll
                    for (int nt = 0; nt < 8; nt++)
                        mma_f16(acc[mt][nt], aHi[ks][mt], bHi[nt]);
#pragma unroll
                for (int mt = 0; mt < 4; mt++)
#pragma unroll
                    for (int nt = 0; nt < 8; nt++)
                        mma_f16(acc[mt][nt], aHi[ks][mt], bLo[nt]);
#pragma unroll
                for (int mt = 0; mt < 4; mt++)
#pragma unroll
                    for (int nt = 0; nt < 8; nt++)
                        mma_f16(acc[mt][nt], aLo[ks][mt], bHi[nt]);
            }
        }

        if (++slot == 3) slot = 0;
    }
}

// ============== persistent Q+K projection ==================================
__global__ void __launch_bounds__(128, 2) gemm_qk(
    const uint32_t* __restrict__ qAH, const uint32_t* __restrict__ qAL,
    const uint32_t* __restrict__ WqH, const uint32_t* __restrict__ WqL,
    const float* __restrict__ bq,
    uint32_t* __restrict__ QH, uint32_t* __restrict__ QL,
    const uint32_t* __restrict__ kAH, const uint32_t* __restrict__ kAL,
    const uint32_t* __restrict__ WkH, const uint32_t* __restrict__ WkL,
    const float* __restrict__ bk,
    uint32_t* __restrict__ KH, uint32_t* __restrict__ KL)
{
    extern __shared__ uint32_t sm[];
    const uint32_t sb0 = (uint32_t)__cvta_generic_to_shared(sm);
    const int lane = threadIdx.x & 31, wid = threadIdx.x >> 5;
    const int warpM = wid & 1, warpN = wid >> 1;
    const int gID = lane >> 2, tig = lane & 3;

    for (int t = blockIdx.x; t < 1024; t += gridDim.x) {
        const int bx = t & 7, by = (t >> 3) & 63, z = t >> 9;
        const int rowBase = by * 128, colBase = bx * 128;
        const uint32_t* AH = z ? kAH : qAH;
        const uint32_t* AL = z ? kAL : qAL;
        const uint32_t* BH = z ? WkH : WqH;
        const uint32_t* BL = z ? WkL : WqL;
        const float* bias = z ? bk : bq;

        float acc[4][8][4];
        gemm_core<3>(sm, sb0, AH, AL, 64, BH, BL, 64, by * 8, bx * 8, 32, acc);

#pragma unroll
        for (int mt = 0; mt < 4; mt++) {
            const int r = rowBase + warpM * 64 + mt * 16 + gID;
#pragma unroll
            for (int nt = 0; nt < 8; nt++) {
                const int c = colBase + warpN * 64 + nt * 8 + tig * 2;
                const float b0 = bias[c], b1 = bias[c + 1];
                const float v00 = acc[mt][nt][0] + b0, v01 = acc[mt][nt][1] + b1;
                const float v10 = acc[mt][nt][2] + b0, v11 = acc[mt][nt][3] + b1;
                const int kp = (c & 15) >> 1;
                uint32_t h0, l0, h1, l1;
                f16_split2(v00, v01, h0, l0);
                f16_split2(v10, v11, h1, l1);
                if (z == 0) {
                    const int lfr = ((r & 7) << 2) | (kp & 3);
                    const int rg0 = (kp >> 2) << 1;
                    const size_t tb = ((size_t)(r >> 4) * 64 + (c >> 4)) * 128 + lfr * 4 + rg0;
                    uint2 uh = {h0, h1}, ul = {l0, l1};
                    *(uint2*)(QH + tb) = uh;
                    *(uint2*)(QL + tb) = ul;
                } else {
                    const int lfr = ((r & 7) << 2) | (kp & 3);
                    const int rg = kp >> 2;
                    const size_t tb = ((size_t)(r >> 4) * 64 + (c >> 4)) * 128 + lfr * 4 + rg;
                    KH[tb] = h0; KH[tb + 2] = h1;
                    KL[tb] = l0; KL[tb + 2] = l1;
                }
            }
        }
    }
}

// ============== persistent V projection (1-pass) ===========================
__global__ void __launch_bounds__(128, 2) gemm_v(
    const uint32_t* __restrict__ vAH, const uint32_t* __restrict__ WvH,
    const float* __restrict__ bv, uint32_t* __restrict__ Vh)
{
    extern __shared__ uint32_t sm[];
    const uint32_t sb0 = (uint32_t)__cvta_generic_to_shared(sm);
    const int lane = threadIdx.x & 31, wid = threadIdx.x >> 5;
    const int warpM = wid & 1, warpN = wid >> 1;
    const int gID = lane >> 2, tig = lane & 3;

    for (int t = blockIdx.x; t < 512; t += gridDim.x) {
        const int bx = t & 7, by = t >> 3;
        const int rowBase = by * 128, colBase = bx * 128;

        float acc[4][8][4];
        gemm_core<1>(sm, sb0, vAH, nullptr, 64, WvH, nullptr, 64, by * 8, bx * 8, 32, acc);

#pragma unroll
        for (int mt = 0; mt < 4; mt++) {
            const int r = rowBase + warpM * 64 + mt * 16 + gID;
#pragma unroll
            for (int nt = 0; nt < 8; nt++) {
                const int c = colBase + warpN * 64 + nt * 8 + tig * 2;
                const float b0 = bv[c], b1 = bv[c + 1];
                Vh[(size_t)r * (MODEL / 2) + (c >> 1)] = f16_pack2(acc[mt][nt][0] + b0, acc[mt][nt][1] + b1);
                Vh[(size_t)(r + 8) * (MODEL / 2) + (c >> 1)] = f16_pack2(acc[mt][nt][2] + b0, acc[mt][nt][3] + b1);
            }
        }
    }
}

// ============== persistent scores (3-pass) =================================
__global__ void __launch_bounds__(128, 2) gemm_s(
    const uint32_t* __restrict__ QH, const uint32_t* __restrict__ QL,
    const uint32_t* __restrict__ KH, const uint32_t* __restrict__ KL,
    float* __restrict__ S)
{
    extern __shared__ uint32_t sm[];
    const uint32_t sb0 = (uint32_t)__cvta_generic_to_shared(sm);
    const int lane = threadIdx.x & 31, wid = threadIdx.x >> 5;
    const int warpM = wid & 1, warpN = wid >> 1;
    const int gID = lane >> 2, tig = lane & 3;

    for (int t = blockIdx.x; t < 1024; t += gridDim.x) {
        const int bx = t & 15, by = (t >> 4) & 15, z = t >> 8;
        const int rowBase = by * 128, colBase = bx * 128;
        float* C = S + (size_t)z * SEQ * SEQ;

        float acc[4][8][4];
        gemm_core<3>(sm, sb0, QH, QL, 64, KH, KL, 64,
                     z * 128 + by * 8, z * 128 + bx * 8, 32, acc);

#pragma unroll
        for (int mt = 0; mt < 4; mt++) {
            const int r = rowBase + warpM * 64 + mt * 16 + gID;
#pragma unroll
            for (int nt = 0; nt < 8; nt++) {
                const int c = colBase + warpN * 64 + nt * 8 + tig * 2;
                float2 o0 = {acc[mt][nt][0] * 0.03125f, acc[mt][nt][1] * 0.03125f};
                float2 o1 = {acc[mt][nt][2] * 0.03125f, acc[mt][nt][3] * 0.03125f};
                *(float2*)(C + (size_t)r * SEQ + c) = o0;
                *(float2*)(C + (size_t)(r + 8) * SEQ + c) = o1;
            }
        }
    }
}

// ============== persistent PV (1-pass) =====================================
__global__ void __launch_bounds__(128, 2) gemm_pv(
    const uint32_t* __restrict__ P, const uint32_t* __restrict__ VT,
    float* __restrict__ O)
{
    extern __shared__ uint32_t sm[];
    const uint32_t sb0 = (uint32_t)__cvta_generic_to_shared(sm);
    const int lane = threadIdx.x & 31, wid = threadIdx.x >> 5;
    const int warpM = wid & 1, warpN = wid >> 1;
    const int gID = lane >> 2, tig = lane & 3;

    for (int t = blockIdx.x; t < 512; t += gridDim.x) {
        const int bx = t & 7, by = (t >> 3) & 15, z = t >> 7;
        const int rowBase = by * 128, colBase = bx * 128;
        float* C = O + (size_t)z * SEQ * MODEL;

        float acc[4][8][4];
        gemm_core<1>(sm, sb0, P, nullptr, SEQ / 16, VT, nullptr, SEQ / 16,
                     z * 128 + by * 8, z * 64 + bx * 8, 64, acc);

#pragma unroll
        for (int mt = 0; mt < 4; mt++) {
            const int r = rowBase + warpM * 64 + mt * 16 + gID;
#pragma unroll
            for (int nt = 0; nt < 8; nt++) {
                const int c = colBase + warpN * 64 + nt * 8 + tig * 2;
                float2 o0 = {acc[mt][nt][0], acc[mt][nt][1]};
                float2 o1 = {acc[mt][nt][2], acc[mt][nt][3]};
                *(float2*)(C + (size_t)r * MODEL + c) = o0;
                *(float2*)(C + (size_t)(r + 8) * MODEL + c) = o1;
            }
        }
    }
}

// ============ merged pre-splits ============================================
__global__ void split_a3(const float* __restrict__ q, const float* __restrict__ k,
                         const float* __restrict__ v,
                         uint32_t* __restrict__ qAH, uint32_t* __restrict__ qAL,
                         uint32_t* __restrict__ kAH, uint32_t* __restrict__ kAL,
                         uint32_t* __restrict__ vAH) {
    const int z = blockIdx.z;
    const float* X = (z == 0) ? q : (z == 1) ? k : v;
    uint32_t* AH = (z == 0) ? qAH : (z == 1) ? kAH : vAH;
    uint32_t* AL = (z == 0) ? qAL : (z == 1) ? kAL : nullptr;

    const size_t idx = (size_t)blockIdx.x * 256 + threadIdx.x;
    const int r = (int)(idx >> 7);
    const int o = (int)(idx & 127);
    const float4 v0 = ((const float4*)X)[idx * 2];
    const float4 v1 = ((const float4*)X)[idx * 2 + 1];
    const float f[8] = {v0.x, v0.y, v0.z, v0.w, v1.x, v1.y, v1.z, v1.w};
    const size_t tbase = ((size_t)(r >> 4) * (MODEL / 16) + (o >> 1)) * 128;
    const int regr = (r >> 3) & 1;
#pragma unroll
    for (int j = 0; j < 4; j++) {
        const int kp = (o & 1) * 4 + j;
        const int w = (((r & 7) << 2) | (kp & 3)) * 4 + (regr | ((kp >> 2) << 1));
        if (AL) {
            uint32_t hi, lo;
            f16_split2(f[2 * j], f[2 * j + 1], hi, lo);
            AH[tbase + w] = hi;
            AL[tbase + w] = lo;
        } else {
            AH[tbase + w] = f16_pack2(f[2 * j], f[2 * j + 1]);
        }
    }
}

// W -> paired B-frag planes of W^T
__global__ void split_b3(const float* __restrict__ Wq, const float* __restrict__ Wk,
                         const float* __restrict__ Wv,
                         uint32_t* __restrict__ WqH, uint32_t* __restrict__ WqL,
                         uint32_t* __restrict__ WkH, uint32_t* __restrict__ WkL,
                         uint32_t* __restrict__ WvH) {
    const int z = blockIdx.z;
    const float* W = (z == 0) ? Wq : (z == 1) ? Wk : Wv;
    uint32_t* BH = (z == 0) ? WqH : (z == 1) ? WkH : WvH;
    uint32_t* BL = (z == 0) ? WqL : (z == 1) ? WkL : nullptr;

    __shared__ float s[64][65];
    const int k0 = blockIdx.y * 64, n0 = blockIdx.x * 64;
#pragma unroll
    for (int i = 0; i < 16; i++) {
        const int e = threadIdx.x + i * 256;
        s[e >> 6][e & 63] = W[(size_t)(k0 + (e >> 6)) * MODEL + n0 + (e & 63)];
    }
    __syncthreads();
#pragma unroll
    for (int i = 0; i < 8; i++) {
        const int e = threadIdx.x + i * 256;
        const int n = e >> 5, kp = e & 31;
        const float a = s[kp * 2][n], b = s[kp * 2 + 1][n];
        const int nG = n0 + n;
        const int kp7 = kp & 7;
        const int lfr = ((nG & 7) << 2) | (kp7 & 3);
        const int sel = (nG >> 3) & 1;
        const int rg = kp7 >> 2;
        const size_t w = ((size_t)(nG >> 4) * (MODEL / 16) + (k0 >> 4) + (kp >> 3)) * 128
                         + lfr * 4 + sel * 2 + rg;
        if (BL) {
            uint32_t hi, lo;
            f16_split2(a, b, hi, lo);
            BH[w] = hi;
            BL[w] = lo;
        } else {
            BH[w] = f16_pack2(a, b);
        }
    }
}

// ============ fused softmax (-> P A-frag plane) + V -> VT paired tiles =====
__global__ void fused_sm_vt(const float* __restrict__ S, uint32_t* __restrict__ P,
                            const uint32_t* __restrict__ Vh, uint32_t* __restrict__ VT) {
    __shared__ float red[8];
    __shared__ uint32_t smv[64][36];

    if (blockIdx.x < MTOT) {
        const int s = blockIdx.x;
        const float* row = S + (size_t)s * SEQ;
        const int tid = threadIdx.x;

        float x[8];
#pragma unroll
        for (int j = 0; j < 4; j++) {
            float2 v = *(const float2*)(row + 2 * (tid + j * 256));
            x[2 * j] = v.x;
            x[2 * j + 1] = v.y;
        }
        float m = x[0];
#pragma unroll
        for (int i = 1; i < 8; i++) m = fmaxf(m, x[i]);
#pragma unroll
        for (int o = 16; o > 0; o >>= 1) m = fmaxf(m, __shfl_xor_sync(0xffffffffu, m, o));
        if ((tid & 31) == 0) red[tid >> 5] = m;
        __syncthreads();
        m = red[0];
#pragma unroll
        for (int i = 1; i < 8; i++) m = fmaxf(m, red[i]);
        __syncthreads();

        float e[8], ssum = 0.0f;
#pragma unroll
        for (int i = 0; i < 8; i++) { e[i] = expf(x[i] - m); ssum += e[i]; }
#pragma unroll
        for (int o = 16; o > 0; o >>= 1) ssum += __shfl_xor_sync(0xffffffffu, ssum, o);
        if ((tid & 31) == 0) red[tid >> 5] = ssum;
        __syncthreads();
        ssum = 0.0f;
#pragma unroll
        for (int i = 0; i < 8; i++) ssum += red[i];
        const float inv = 1.0f / ssum;

        const int laneRow = (s & 7) << 2;
        const int regRow = (s >> 3) & 1;
        const size_t mtOff = (size_t)(s >> 4) * 128;
#pragma unroll
        for (int j = 0; j < 4; j++) {
            const int cp = tid + j * 256;
            const int pl = cp & 7, kt = cp >> 3;
            const int lfr = laneRow | (pl & 3);
            const int rg = regRow | ((pl >> 2) << 1);
            P[(mtOff + kt) * 128 + lfr * 4 + rg] = f16_pack2(e[2 * j] * inv, e[2 * j + 1] * inv);
        }
    } else {
        const int b = blockIdx.x - MTOT;
        const int z = b >> 9;
        const int t0 = ((b >> 4) & 31) * 64;
        const int d0 = (b & 15) * 64;
        const int tr = threadIdx.x >> 3, dq = threadIdx.x & 7;
#pragma unroll
        for (int i = 0; i < 2; i++) {
            const int t = tr + i * 32;
            *(uint4*)&smv[t][dq * 4] =
                *(const uint4*)(Vh + (size_t)(z * SEQ + t0 + t) * (MODEL / 2) + (d0 >> 1) + dq * 4);
        }
        __syncthreads();
#pragma unroll
        for (int i = 0; i < 8; i++) {
            const int idx = threadIdx.x + i * 256;
            const int tile = idx >> 6, within = idx & 63;
            const int lfr = within >> 1, rg = within & 1;
            const int ntl = tile >> 2, ktl = tile & 3;
            const int n = ntl * 8 + (lfr >> 2);
            const int p = (lfr & 3) | (rg << 2);
            const int k = ktl * 16 + p * 2;
            const uint32_t a = smv[k][n >> 1], bb = smv[k + 1][n >> 1];
            const uint32_t h0 = (n & 1) ? (a >> 16) : (a & 0xffffu);
            const uint32_t h1 = (n & 1) ? (bb >> 16) : (bb & 0xffffu);
            const int gtile = (d0 >> 3) + ntl;
            const size_t addr = ((size_t)(z * 64 + (gtile >> 1)) * (SEQ / 16)
                                 + (t0 >> 4) + ktl) * 128
                                + lfr * 4 + (gtile & 1) * 2 + rg;
            VT[addr] = h0 | (h1 << 16);
        }
    }
}

// ------------------------------- launcher ----------------------------------
extern "C" void kernel_launch(void* const* d_in, const int* in_sizes, int n_in,
                              void* d_out, int out_size) {
    const float* q  = (const float*)d_in[0];
    const float* k  = (const float*)d_in[1];
    const float* v  = (const float*)d_in[2];
    const float* Wq = (const float*)d_in[3];
    const float* Wk = (const float*)d_in[4];
    const float* Wv = (const float*)d_in[5];
    const float* bq = (const float*)d_in[6];
    const float* bk = (const float*)d_in[7];
    const float* bv = (const float*)d_in[8];
    float* out = (float*)d_out;

    uint32_t *qAH, *qAL, *kAH, *kAL, *vAH;
    uint32_t *WqH, *WqL, *WkH, *WkL, *WvH;
    uint32_t *QH, *QL, *KH, *KL, *Vh, *VT, *P;
    float* Sp;
    cudaGetSymbolAddress((void**)&qAH, g_qAH);
    cudaGetSymbolAddress((void**)&qAL, g_qAL);
    cudaGetSymbolAddress((void**)&kAH, g_kAH);
    cudaGetSymbolAddress((void**)&kAL, g_kAL);
    cudaGetSymbolAddress((void**)&vAH, g_vAH);
    cudaGetSymbolAddress((void**)&WqH, g_WqH);
    cudaGetSymbolAddress((void**)&WqL, g_WqL);
    cudaGetSymbolAddress((void**)&WkH, g_WkH);
    cudaGetSymbolAddress((void**)&WkL, g_WkL);
    cudaGetSymbolAddress((void**)&WvH, g_WvH);
    cudaGetSymbolAddress((void**)&QH, g_QH);
    cudaGetSymbolAddress((void**)&QL, g_QL);
    cudaGetSymbolAddress((void**)&KH, g_KH);
    cudaGetSymbolAddress((void**)&KL, g_KL);
    cudaGetSymbolAddress((void**)&Vh, g_Vh);
    cudaGetSymbolAddress((void**)&VT, g_VT);
    cudaGetSymbolAddress((void**)&P,  g_P);
    cudaGetSymbolAddress((void**)&Sp, g_S);

    static int smem_set = 0;
    if (!smem_set) {
        cudaFuncSetAttribute(gemm_qk, cudaFuncAttributeMaxDynamicSharedMemorySize, 98304);
        cudaFuncSetAttribute(gemm_s,  cudaFuncAttributeMaxDynamicSharedMemorySize, 98304);
        smem_set = 1;
    }

    split_a3<<<dim3(4096, 1, 3), 256>>>(q, k, v, qAH, qAL, kAH, kAL, vAH);
    split_b3<<<dim3(16, 16, 3), 256>>>(Wq, Wk, Wv, WqH, WqL, WkH, WkL, WvH);

    gemm_qk<<<PERSIST, 128, 98304>>>(qAH, qAL, WqH, WqL, bq, QH, QL,
                                     kAH, kAL, WkH, WkL, bk, KH, KL);
    gemm_v<<<PERSIST, 128, 49152>>>(vAH, WvH, bv, Vh);

    gemm_s<<<PERSIST, 128, 98304>>>(QH, QL, KH, KL, Sp);

    fused_sm_vt<<<MTOT + 2048, 256>>>(Sp, P, Vh, VT);

    gemm_pv<<<PERSIST, 128, 49152>>>(P, VT, out);
}

// round 16
// speedup vs baseline: 1.0062x; 1.0062x over previous
#include <cuda_runtime.h>
#include <cuda_fp16.h>
#include <cstdint>
#include <math.h>

// ---------------------------------------------------------------------------
// DotProductAttention (sm_103 plain -> mma.sync m16n8k16 fp16).
// R16: R14 GEMM pipeline (best: 663.6us) + sparse-exp softmax: skip expf for
// x - m < -17.5 (those P entries round to 0 in fp16 regardless). MUFU work
// drops 16.8M -> ~100K exps; softmax becomes memory-bound.
// ---------------------------------------------------------------------------

#define BATCH 4
#define SEQ   2048
#define MODEL 1024
#define MTOT  (BATCH * SEQ)   // 8192
#define PERSIST 296

__device__ uint32_t g_qAH[(size_t)MTOT * MODEL / 2];
__device__ uint32_t g_qAL[(size_t)MTOT * MODEL / 2];
__device__ uint32_t g_kAH[(size_t)MTOT * MODEL / 2];
__device__ uint32_t g_kAL[(size_t)MTOT * MODEL / 2];
__device__ uint32_t g_vAH[(size_t)MTOT * MODEL / 2];
__device__ uint32_t g_WqH[MODEL * MODEL / 2];
__device__ uint32_t g_WqL[MODEL * MODEL / 2];
__device__ uint32_t g_WkH[MODEL * MODEL / 2];
__device__ uint32_t g_WkL[MODEL * MODEL / 2];
__device__ uint32_t g_WvH[MODEL * MODEL / 2];
__device__ uint32_t g_QH[(size_t)MTOT * MODEL / 2];
__device__ uint32_t g_QL[(size_t)MTOT * MODEL / 2];
__device__ uint32_t g_KH[(size_t)MTOT * MODEL / 2];
__device__ uint32_t g_KL[(size_t)MTOT * MODEL / 2];
__device__ uint32_t g_Vh[(size_t)MTOT * MODEL / 2];
__device__ uint32_t g_VT[(size_t)BATCH * (MODEL / 8) * (SEQ / 16) * 64];
__device__ uint32_t g_P [(size_t)MTOT * (SEQ / 2)];
__device__ float    g_S [(size_t)BATCH * SEQ * SEQ];

__device__ __forceinline__ void f16_split2(float a, float b, uint32_t& hi, uint32_t& lo) {
    __half ha = __float2half_rn(a), hb = __float2half_rn(b);
    __half la = __float2half_rn(a - __half2float(ha));
    __half lb = __float2half_rn(b - __half2float(hb));
    hi = ((uint32_t)__half_as_ushort(hb) << 16) | (uint32_t)__half_as_ushort(ha);
    lo = ((uint32_t)__half_as_ushort(lb) << 16) | (uint32_t)__half_as_ushort(la);
}
__device__ __forceinline__ uint32_t f16_pack2(float a, float b) {
    __half ha = __float2half_rn(a), hb = __float2half_rn(b);
    return ((uint32_t)__half_as_ushort(hb) << 16) | (uint32_t)__half_as_ushort(ha);
}
__device__ __forceinline__ void mma_f16(float* c, const uint32_t* a, const uint32_t* b) {
    asm volatile(
        "mma.sync.aligned.m16n8k16.row.col.f32.f16.f16.f32 "
        "{%0,%1,%2,%3}, {%4,%5,%6,%7}, {%8,%9}, {%0,%1,%2,%3};"
        : "+f"(c[0]), "+f"(c[1]), "+f"(c[2]), "+f"(c[3])
        : "r"(a[0]), "r"(a[1]), "r"(a[2]), "r"(a[3]), "r"(b[0]), "r"(b[1]));
}
__device__ __forceinline__ void cp16(uint32_t s, const void* g) {
    asm volatile("cp.async.cg.shared.global [%0], [%1], 16;" :: "r"(s), "l"(g));
}
__device__ __forceinline__ void cp_commit() { asm volatile("cp.async.commit_group;" ::: "memory"); }
template <int N> __device__ __forceinline__ void cp_wait() {
    asm volatile("cp.async.wait_group %0;" :: "n"(N) : "memory");
}

// ========== shared GEMM core: BK=32, 3-stage ring, paired-B planes =========
template <int PASSES>
__device__ __forceinline__ void gemm_core(
    uint32_t* smBase, uint32_t sb0,
    const uint32_t* __restrict__ AH, const uint32_t* __restrict__ AL, int nktA,
    const uint32_t* __restrict__ BH, const uint32_t* __restrict__ BL, int nktB,
    int mtBase, int pBase, int nk32, float (&acc)[4][8][4])
{
    constexpr bool P3 = (PASSES == 3);
    constexpr int OFF_ALO = 2048;
    constexpr int OFF_B  = P3 ? 4096 : 2048;
    constexpr int OFF_BLO = OFF_B + 2048;
    constexpr int STG = P3 ? 8192 : 4096;

    const int tid = threadIdx.x, wid = tid >> 5, lane = tid & 31;
    const int warpM = wid & 1, warpN = wid >> 1;

    const uint32_t *pA[4], *pAl[4], *pB[4], *pBl[4];
    uint32_t dOff[4];
#pragma unroll
    for (int j = 0; j < 4; j++) {
        const int gi = tid + j * 128;
        const int ks = gi >> 8;
        const int blk = (gi >> 5) & 7;
        const int w = (gi & 31) * 4;
        dOff[j] = (uint32_t)(ks * 1024 + blk * 128 + w);
        pA[j] = AH + ((size_t)(mtBase + blk) * nktA + ks) * 128 + w;
        pB[j] = BH + ((size_t)(pBase + blk) * nktB + ks) * 128 + w;
        if (P3) {
            pAl[j] = AL + ((size_t)(mtBase + blk) * nktA + ks) * 128 + w;
            pBl[j] = BL + ((size_t)(pBase + blk) * nktB + ks) * 128 + w;
        }
    }

    auto issue = [&](int it, int stg) {
        const uint32_t s = sb0 + stg * (STG * 4);
        const size_t kadd = (size_t)it * 256;
#pragma unroll
        for (int j = 0; j < 4; j++) {
            cp16(s + dOff[j] * 4, pA[j] + kadd);
            if (P3) cp16(s + (OFF_ALO + dOff[j]) * 4, pAl[j] + kadd);
            cp16(s + (OFF_B + dOff[j]) * 4, pB[j] + kadd);
            if (P3) cp16(s + (OFF_BLO + dOff[j]) * 4, pBl[j] + kadd);
        }
        cp_commit();
    };

#pragma unroll
    for (int mt = 0; mt < 4; mt++)
#pragma unroll
        for (int nt = 0; nt < 8; nt++)
#pragma unroll
            for (int e = 0; e < 4; e++) acc[mt][nt][e] = 0.0f;

    __syncthreads();
    issue(0, 0);
    issue(1, 1);

    int slot = 0;
    for (int i = 0; i < nk32; i++) {
        if (i + 1 < nk32) cp_wait<1>();
        else              cp_wait<0>();
        __syncthreads();

        if (i + 2 < nk32) {
            int nslot = slot + 2;
            if (nslot >= 3) nslot -= 3;
            issue(i + 2, nslot);
        }

        const uint32_t* s = smBase + slot * STG;
#pragma unroll
        for (int ks = 0; ks < 2; ks++) {
            const uint32_t* sl = s + ks * 1024;
            uint32_t aHi[4][4], aLo[4][4], bHi[8][2], bLo[8][2];
#pragma unroll
            for (int mt = 0; mt < 4; mt++) {
                const uint32_t* ap = sl + (warpM * 4 + mt) * 128 + lane * 4;
                *(uint4*)aHi[mt] = *(const uint4*)ap;
                if (P3) *(uint4*)aLo[mt] = *(const uint4*)(ap + OFF_ALO);
            }
#pragma unroll
            for (int pp = 0; pp < 4; pp++) {
                const uint32_t* bp = sl + OFF_B + (warpN * 4 + pp) * 128 + lane * 4;
                const uint4 bh = *(const uint4*)bp;
                bHi[2 * pp][0] = bh.x; bHi[2 * pp][1] = bh.y;
                bHi[2 * pp + 1][0] = bh.z; bHi[2 * pp + 1][1] = bh.w;
                if (P3) {
                    const uint4 bl = *(const uint4*)(bp + 2048);
                    bLo[2 * pp][0] = bl.x; bLo[2 * pp][1] = bl.y;
                    bLo[2 * pp + 1][0] = bl.z; bLo[2 * pp + 1][1] = bl.w;
                }
            }
#pragma unroll
            for (int mt = 0; mt < 4; mt++)
#pragma unroll
                for (int nt = 0; nt < 8; nt++)
                    mma_f16(acc[mt][nt], aHi[mt], bHi[nt]);
            if (P3) {
#pragma unroll
                for (int mt = 0; mt < 4; mt++)
#pragma unroll
                    for (int nt = 0; nt < 8; nt++)
                        mma_f16(acc[mt][nt], aHi[mt], bLo[nt]);
#pragma unroll
                for (int mt = 0; mt < 4; mt++)
#pragma unroll
                    for (int nt = 0; nt < 8; nt++)
                        mma_f16(acc[mt][nt], aLo[mt], bHi[nt]);
            }
        }

        if (++slot == 3) slot = 0;
    }
}

// ============== persistent Q+K projection ==================================
__global__ void __launch_bounds__(128, 2) gemm_qk(
    const uint32_t* __restrict__ qAH, const uint32_t* __restrict__ qAL,
    const uint32_t* __restrict__ WqH, const uint32_t* __restrict__ WqL,
    const float* __restrict__ bq,
    uint32_t* __restrict__ QH, uint32_t* __restrict__ QL,
    const uint32_t* __restrict__ kAH, const uint32_t* __restrict__ kAL,
    const uint32_t* __restrict__ WkH, const uint32_t* __restrict__ WkL,
    const float* __restrict__ bk,
    uint32_t* __restrict__ KH, uint32_t* __restrict__ KL)
{
    extern __shared__ uint32_t sm[];
    const uint32_t sb0 = (uint32_t)__cvta_generic_to_shared(sm);
    const int lane = threadIdx.x & 31, wid = threadIdx.x >> 5;
    const int warpM = wid & 1, warpN = wid >> 1;
    const int gID = lane >> 2, tig = lane & 3;

    for (int t = blockIdx.x; t < 1024; t += gridDim.x) {
        const int bx = t & 7, by = (t >> 3) & 63, z = t >> 9;
        const int rowBase = by * 128, colBase = bx * 128;
        const uint32_t* AH = z ? kAH : qAH;
        const uint32_t* AL = z ? kAL : qAL;
        const uint32_t* BH = z ? WkH : WqH;
        const uint32_t* BL = z ? WkL : WqL;
        const float* bias = z ? bk : bq;

        float acc[4][8][4];
        gemm_core<3>(sm, sb0, AH, AL, 64, BH, BL, 64, by * 8, bx * 8, 32, acc);

#pragma unroll
        for (int mt = 0; mt < 4; mt++) {
            const int r = rowBase + warpM * 64 + mt * 16 + gID;
#pragma unroll
            for (int nt = 0; nt < 8; nt++) {
                const int c = colBase + warpN * 64 + nt * 8 + tig * 2;
                const float b0 = bias[c], b1 = bias[c + 1];
                const float v00 = acc[mt][nt][0] + b0, v01 = acc[mt][nt][1] + b1;
                const float v10 = acc[mt][nt][2] + b0, v11 = acc[mt][nt][3] + b1;
                const int kp = (c & 15) >> 1;
                uint32_t h0, l0, h1, l1;
                f16_split2(v00, v01, h0, l0);
                f16_split2(v10, v11, h1, l1);
                if (z == 0) {
                    const int lfr = ((r & 7) << 2) | (kp & 3);
                    const int rg0 = (kp >> 2) << 1;
                    const size_t tb = ((size_t)(r >> 4) * 64 + (c >> 4)) * 128 + lfr * 4 + rg0;
                    uint2 uh = {h0, h1}, ul = {l0, l1};
                    *(uint2*)(QH + tb) = uh;
                    *(uint2*)(QL + tb) = ul;
                } else {
                    const int lfr = ((r & 7) << 2) | (kp & 3);
                    const int rg = kp >> 2;
                    const size_t tb = ((size_t)(r >> 4) * 64 + (c >> 4)) * 128 + lfr * 4 + rg;
                    KH[tb] = h0; KH[tb + 2] = h1;
                    KL[tb] = l0; KL[tb + 2] = l1;
                }
            }
        }
    }
}

// ============== persistent V projection (1-pass) ===========================
__global__ void __launch_bounds__(128, 2) gemm_v(
    const uint32_t* __restrict__ vAH, const uint32_t* __restrict__ WvH,
    const float* __restrict__ bv, uint32_t* __restrict__ Vh)
{
    extern __shared__ uint32_t sm[];
    const uint32_t sb0 = (uint32_t)__cvta_generic_to_shared(sm);
    const int lane = threadIdx.x & 31, wid = threadIdx.x >> 5;
    const int warpM = wid & 1, warpN = wid >> 1;
    const int gID = lane >> 2, tig = lane & 3;

    for (int t = blockIdx.x; t < 512; t += gridDim.x) {
        const int bx = t & 7, by = t >> 3;
        const int rowBase = by * 128, colBase = bx * 128;

        float acc[4][8][4];
        gemm_core<1>(sm, sb0, vAH, nullptr, 64, WvH, nullptr, 64, by * 8, bx * 8, 32, acc);

#pragma unroll
        for (int mt = 0; mt < 4; mt++) {
            const int r = rowBase + warpM * 64 + mt * 16 + gID;
#pragma unroll
            for (int nt = 0; nt < 8; nt++) {
                const int c = colBase + warpN * 64 + nt * 8 + tig * 2;
                const float b0 = bv[c], b1 = bv[c + 1];
                Vh[(size_t)r * (MODEL / 2) + (c >> 1)] = f16_pack2(acc[mt][nt][0] + b0, acc[mt][nt][1] + b1);
                Vh[(size_t)(r + 8) * (MODEL / 2) + (c >> 1)] = f16_pack2(acc[mt][nt][2] + b0, acc[mt][nt][3] + b1);
            }
        }
    }
}

// ============== persistent scores (3-pass) =================================
__global__ void __launch_bounds__(128, 2) gemm_s(
    const uint32_t* __restrict__ QH, const uint32_t* __restrict__ QL,
    const uint32_t* __restrict__ KH, const uint32_t* __restrict__ KL,
    float* __restrict__ S)
{
    extern __shared__ uint32_t sm[];
    const uint32_t sb0 = (uint32_t)__cvta_generic_to_shared(sm);
    const int lane = threadIdx.x & 31, wid = threadIdx.x >> 5;
    const int warpM = wid & 1, warpN = wid >> 1;
    const int gID = lane >> 2, tig = lane & 3;

    for (int t = blockIdx.x; t < 1024; t += gridDim.x) {
        const int bx = t & 15, by = (t >> 4) & 15, z = t >> 8;
        const int rowBase = by * 128, colBase = bx * 128;
        float* C = S + (size_t)z * SEQ * SEQ;

        float acc[4][8][4];
        gemm_core<3>(sm, sb0, QH, QL, 64, KH, KL, 64,
                     z * 128 + by * 8, z * 128 + bx * 8, 32, acc);

#pragma unroll
        for (int mt = 0; mt < 4; mt++) {
            const int r = rowBase + warpM * 64 + mt * 16 + gID;
#pragma unroll
            for (int nt = 0; nt < 8; nt++) {
                const int c = colBase + warpN * 64 + nt * 8 + tig * 2;
                float2 o0 = {acc[mt][nt][0] * 0.03125f, acc[mt][nt][1] * 0.03125f};
                float2 o1 = {acc[mt][nt][2] * 0.03125f, acc[mt][nt][3] * 0.03125f};
                *(float2*)(C + (size_t)r * SEQ + c) = o0;
                *(float2*)(C + (size_t)(r + 8) * SEQ + c) = o1;
            }
        }
    }
}

// ============== persistent PV (1-pass) =====================================
__global__ void __launch_bounds__(128, 2) gemm_pv(
    const uint32_t* __restrict__ P, const uint32_t* __restrict__ VT,
    float* __restrict__ O)
{
    extern __shared__ uint32_t sm[];
    const uint32_t sb0 = (uint32_t)__cvta_generic_to_shared(sm);
    const int lane = threadIdx.x & 31, wid = threadIdx.x >> 5;
    const int warpM = wid & 1, warpN = wid >> 1;
    const int gID = lane >> 2, tig = lane & 3;

    for (int t = blockIdx.x; t < 512; t += gridDim.x) {
        const int bx = t & 7, by = (t >> 3) & 15, z = t >> 7;
        const int rowBase = by * 128, colBase = bx * 128;
        float* C = O + (size_t)z * SEQ * MODEL;

        float acc[4][8][4];
        gemm_core<1>(sm, sb0, P, nullptr, SEQ / 16, VT, nullptr, SEQ / 16,
                     z * 128 + by * 8, z * 64 + bx * 8, 64, acc);

#pragma unroll
        for (int mt = 0; mt < 4; mt++) {
            const int r = rowBase + warpM * 64 + mt * 16 + gID;
#pragma unroll
            for (int nt = 0; nt < 8; nt++) {
                const int c = colBase + warpN * 64 + nt * 8 + tig * 2;
                float2 o0 = {acc[mt][nt][0], acc[mt][nt][1]};
                float2 o1 = {acc[mt][nt][2], acc[mt][nt][3]};
                *(float2*)(C + (size_t)r * MODEL + c) = o0;
                *(float2*)(C + (size_t)(r + 8) * MODEL + c) = o1;
            }
        }
    }
}

// ============ merged pre-splits ============================================
__global__ void split_a3(const float* __restrict__ q, const float* __restrict__ k,
                         const float* __restrict__ v,
                         uint32_t* __restrict__ qAH, uint32_t* __restrict__ qAL,
                         uint32_t* __restrict__ kAH, uint32_t* __restrict__ kAL,
                         uint32_t* __restrict__ vAH) {
    const int z = blockIdx.z;
    const float* X = (z == 0) ? q : (z == 1) ? k : v;
    uint32_t* AH = (z == 0) ? qAH : (z == 1) ? kAH : vAH;
    uint32_t* AL = (z == 0) ? qAL : (z == 1) ? kAL : nullptr;

    const size_t idx = (size_t)blockIdx.x * 256 + threadIdx.x;
    const int r = (int)(idx >> 7);
    const int o = (int)(idx & 127);
    const float4 v0 = ((const float4*)X)[idx * 2];
    const float4 v1 = ((const float4*)X)[idx * 2 + 1];
    const float f[8] = {v0.x, v0.y, v0.z, v0.w, v1.x, v1.y, v1.z, v1.w};
    const size_t tbase = ((size_t)(r >> 4) * (MODEL / 16) + (o >> 1)) * 128;
    const int regr = (r >> 3) & 1;
#pragma unroll
    for (int j = 0; j < 4; j++) {
        const int kp = (o & 1) * 4 + j;
        const int w = (((r & 7) << 2) | (kp & 3)) * 4 + (regr | ((kp >> 2) << 1));
        if (AL) {
            uint32_t hi, lo;
            f16_split2(f[2 * j], f[2 * j + 1], hi, lo);
            AH[tbase + w] = hi;
            AL[tbase + w] = lo;
        } else {
            AH[tbase + w] = f16_pack2(f[2 * j], f[2 * j + 1]);
        }
    }
}

// W -> paired B-frag planes of W^T
__global__ void split_b3(const float* __restrict__ Wq, const float* __restrict__ Wk,
                         const float* __restrict__ Wv,
                         uint32_t* __restrict__ WqH, uint32_t* __restrict__ WqL,
                         uint32_t* __restrict__ WkH, uint32_t* __restrict__ WkL,
                         uint32_t* __restrict__ WvH) {
    const int z = blockIdx.z;
    const float* W = (z == 0) ? Wq : (z == 1) ? Wk : Wv;
    uint32_t* BH = (z == 0) ? WqH : (z == 1) ? WkH : WvH;
    uint32_t* BL = (z == 0) ? WqL : (z == 1) ? WkL : nullptr;

    __shared__ float s[64][65];
    const int k0 = blockIdx.y * 64, n0 = blockIdx.x * 64;
#pragma unroll
    for (int i = 0; i < 16; i++) {
        const int e = threadIdx.x + i * 256;
        s[e >> 6][e & 63] = W[(size_t)(k0 + (e >> 6)) * MODEL + n0 + (e & 63)];
    }
    __syncthreads();
#pragma unroll
    for (int i = 0; i < 8; i++) {
        const int e = threadIdx.x + i * 256;
        const int n = e >> 5, kp = e & 31;
        const float a = s[kp * 2][n], b = s[kp * 2 + 1][n];
        const int nG = n0 + n;
        const int kp7 = kp & 7;
        const int lfr = ((nG & 7) << 2) | (kp7 & 3);
        const int sel = (nG >> 3) & 1;
        const int rg = kp7 >> 2;
        const size_t w = ((size_t)(nG >> 4) * (MODEL / 16) + (k0 >> 4) + (kp >> 3)) * 128
                         + lfr * 4 + sel * 2 + rg;
        if (BL) {
            uint32_t hi, lo;
            f16_split2(a, b, hi, lo);
            BH[w] = hi;
            BL[w] = lo;
        } else {
            BH[w] = f16_pack2(a, b);
        }
    }
}

// ============ fused softmax (sparse exp) + V -> VT paired tiles ============
__global__ void fused_sm_vt(const float* __restrict__ S, uint32_t* __restrict__ P,
                            const uint32_t* __restrict__ Vh, uint32_t* __restrict__ VT) {
    __shared__ float red[8];
    __shared__ uint32_t smv[64][36];

    if (blockIdx.x < MTOT) {
        const int s = blockIdx.x;
        const float* row = S + (size_t)s * SEQ;
        const int tid = threadIdx.x;

        float x[8];
#pragma unroll
        for (int j = 0; j < 4; j++) {
            float2 v = *(const float2*)(row + 2 * (tid + j * 256));
            x[2 * j] = v.x;
            x[2 * j + 1] = v.y;
        }
        float m = x[0];
#pragma unroll
        for (int i = 1; i < 8; i++) m = fmaxf(m, x[i]);
#pragma unroll
        for (int o = 16; o > 0; o >>= 1) m = fmaxf(m, __shfl_xor_sync(0xffffffffu, m, o));
        if ((tid & 31) == 0) red[tid >> 5] = m;
        __syncthreads();
        m = red[0];
#pragma unroll
        for (int i = 1; i < 8; i++) m = fmaxf(m, red[i]);
        __syncthreads();

        // sparse exp: terms with x-m < -17.5 give P < 2.5e-8 -> 0 in fp16 anyway.
        float e[8], ssum = 0.0f;
        bool live = false;
#pragma unroll
        for (int i = 0; i < 8; i++) live |= (x[i] - m > -17.5f);
        if (__any_sync(0xffffffffu, live)) {
#pragma unroll
            for (int i = 0; i < 8; i++) {
                const float d = x[i] - m;
                e[i] = (d > -17.5f) ? expf(d) : 0.0f;
                ssum += e[i];
            }
        } else {
#pragma unroll
            for (int i = 0; i < 8; i++) e[i] = 0.0f;
        }
#pragma unroll
        for (int o = 16; o > 0; o >>= 1) ssum += __shfl_xor_sync(0xffffffffu, ssum, o);
        if ((tid & 31) == 0) red[tid >> 5] = ssum;
        __syncthreads();
        ssum = 0.0f;
#pragma unroll
        for (int i = 0; i < 8; i++) ssum += red[i];
        const float inv = 1.0f / ssum;

        const int laneRow = (s & 7) << 2;
        const int regRow = (s >> 3) & 1;
        const size_t mtOff = (size_t)(s >> 4) * 128;
#pragma unroll
        for (int j = 0; j < 4; j++) {
            const int cp = tid + j * 256;
            const int pl = cp & 7, kt = cp >> 3;
            const int lfr = laneRow | (pl & 3);
            const int rg = regRow | ((pl >> 2) << 1);
            P[(mtOff + kt) * 128 + lfr * 4 + rg] = f16_pack2(e[2 * j] * inv, e[2 * j + 1] * inv);
        }
    } else {
        const int b = blockIdx.x - MTOT;
        const int z = b >> 9;
        const int t0 = ((b >> 4) & 31) * 64;
        const int d0 = (b & 15) * 64;
        const int tr = threadIdx.x >> 3, dq = threadIdx.x & 7;
#pragma unroll
        for (int i = 0; i < 2; i++) {
            const int t = tr + i * 32;
            *(uint4*)&smv[t][dq * 4] =
                *(const uint4*)(Vh + (size_t)(z * SEQ + t0 + t) * (MODEL / 2) + (d0 >> 1) + dq * 4);
        }
        __syncthreads();
#pragma unroll
        for (int i = 0; i < 8; i++) {
            const int idx = threadIdx.x + i * 256;
            const int tile = idx >> 6, within = idx & 63;
            const int lfr = within >> 1, rg = within & 1;
            const int ntl = tile >> 2, ktl = tile & 3;
            const int n = ntl * 8 + (lfr >> 2);
            const int p = (lfr & 3) | (rg << 2);
            const int k = ktl * 16 + p * 2;
            const uint32_t a = smv[k][n >> 1], bb = smv[k + 1][n >> 1];
            const uint32_t h0 = (n & 1) ? (a >> 16) : (a & 0xffffu);
            const uint32_t h1 = (n & 1) ? (bb >> 16) : (bb & 0xffffu);
            const int gtile = (d0 >> 3) + ntl;
            const size_t addr = ((size_t)(z * 64 + (gtile >> 1)) * (SEQ / 16)
                                 + (t0 >> 4) + ktl) * 128
                                + lfr * 4 + (gtile & 1) * 2 + rg;
            VT[addr] = h0 | (h1 << 16);
        }
    }
}

// ------------------------------- launcher ----------------------------------
extern "C" void kernel_launch(void* const* d_in, const int* in_sizes, int n_in,
                              void* d_out, int out_size) {
    const float* q  = (const float*)d_in[0];
    const float* k  = (const float*)d_in[1];
    const float* v  = (const float*)d_in[2];
    const float* Wq = (const float*)d_in[3];
    const float* Wk = (const float*)d_in[4];
    const float* Wv = (const float*)d_in[5];
    const float* bq = (const float*)d_in[6];
    const float* bk = (const float*)d_in[7];
    const float* bv = (const float*)d_in[8];
    float* out = (float*)d_out;

    uint32_t *qAH, *qAL, *kAH, *kAL, *vAH;
    uint32_t *WqH, *WqL, *WkH, *WkL, *WvH;
    uint32_t *QH, *QL, *KH, *KL, *Vh, *VT, *P;
    float* Sp;
    cudaGetSymbolAddress((void**)&qAH, g_qAH);
    cudaGetSymbolAddress((void**)&qAL, g_qAL);
    cudaGetSymbolAddress((void**)&kAH, g_kAH);
    cudaGetSymbolAddress((void**)&kAL, g_kAL);
    cudaGetSymbolAddress((void**)&vAH, g_vAH);
    cudaGetSymbolAddress((void**)&WqH, g_WqH);
    cudaGetSymbolAddress((void**)&WqL, g_WqL);
    cudaGetSymbolAddress((void**)&WkH, g_WkH);
    cudaGetSymbolAddress((void**)&WkL, g_WkL);
    cudaGetSymbolAddress((void**)&WvH, g_WvH);
    cudaGetSymbolAddress((void**)&QH, g_QH);
    cudaGetSymbolAddress((void**)&QL, g_QL);
    cudaGetSymbolAddress((void**)&KH, g_KH);
    cudaGetSymbolAddress((void**)&KL, g_KL);
    cudaGetSymbolAddress((void**)&Vh, g_Vh);
    cudaGetSymbolAddress((void**)&VT, g_VT);
    cudaGetSymbolAddress((void**)&P,  g_P);
    cudaGetSymbolAddress((void**)&Sp, g_S);

    static int smem_set = 0;
    if (!smem_set) {
        cudaFuncSetAttribute(gemm_qk, cudaFuncAttributeMaxDynamicSharedMemorySize, 98304);
        cudaFuncSetAttribute(gemm_s,  cudaFuncAttributeMaxDynamicSharedMemorySize, 98304);
        smem_set = 1;
    }

    split_a3<<<dim3(4096, 1, 3), 256>>>(q, k, v, qAH, qAL, kAH, kAL, vAH);
    split_b3<<<dim3(16, 16, 3), 256>>>(Wq, Wk, Wv, WqH, WqL, WkH, WkL, WvH);

    gemm_qk<<<PERSIST, 128, 98304>>>(qAH, qAL, WqH, WqL, bq, QH, QL,
                                     kAH, kAL, WkH, WkL, bk, KH, KL);
    gemm_v<<<PERSIST, 128, 49152>>>(vAH, WvH, bv, Vh);

    gemm_s<<<PERSIST, 128, 98304>>>(QH, QL, KH, KL, Sp);

    fused_sm_vt<<<MTOT + 2048, 256>>>(Sp, P, Vh, VT);

    gemm_pv<<<PERSIST, 128, 49152>>>(P, VT, out);
}

// round 17
// speedup vs baseline: 1.0447x; 1.0382x over previous
#include <cuda_runtime.h>
#include <cuda_fp16.h>
#include <cstdint>
#include <math.h>

// ---------------------------------------------------------------------------
// DotProductAttention (sm_103 plain -> mma.sync m16n8k16 fp16).
// R17: merge V-proj into the QK persistent tile queue (better tail fill),
// smem-staged coalesced split_a3. GEMM cores identical to R14/R16 best.
// ---------------------------------------------------------------------------

#define BATCH 4
#define SEQ   2048
#define MODEL 1024
#define MTOT  (BATCH * SEQ)   // 8192
#define PERSIST 296

__device__ uint32_t g_qAH[(size_t)MTOT * MODEL / 2];
__device__ uint32_t g_qAL[(size_t)MTOT * MODEL / 2];
__device__ uint32_t g_kAH[(size_t)MTOT * MODEL / 2];
__device__ uint32_t g_kAL[(size_t)MTOT * MODEL / 2];
__device__ uint32_t g_vAH[(size_t)MTOT * MODEL / 2];
__device__ uint32_t g_WqH[MODEL * MODEL / 2];
__device__ uint32_t g_WqL[MODEL * MODEL / 2];
__device__ uint32_t g_WkH[MODEL * MODEL / 2];
__device__ uint32_t g_WkL[MODEL * MODEL / 2];
__device__ uint32_t g_WvH[MODEL * MODEL / 2];
__device__ uint32_t g_QH[(size_t)MTOT * MODEL / 2];
__device__ uint32_t g_QL[(size_t)MTOT * MODEL / 2];
__device__ uint32_t g_KH[(size_t)MTOT * MODEL / 2];
__device__ uint32_t g_KL[(size_t)MTOT * MODEL / 2];
__device__ uint32_t g_Vh[(size_t)MTOT * MODEL / 2];
__device__ uint32_t g_VT[(size_t)BATCH * (MODEL / 8) * (SEQ / 16) * 64];
__device__ uint32_t g_P [(size_t)MTOT * (SEQ / 2)];
__device__ float    g_S [(size_t)BATCH * SEQ * SEQ];

__device__ __forceinline__ void f16_split2(float a, float b, uint32_t& hi, uint32_t& lo) {
    __half ha = __float2half_rn(a), hb = __float2half_rn(b);
    __half la = __float2half_rn(a - __half2float(ha));
    __half lb = __float2half_rn(b - __half2float(hb));
    hi = ((uint32_t)__half_as_ushort(hb) << 16) | (uint32_t)__half_as_ushort(ha);
    lo = ((uint32_t)__half_as_ushort(lb) << 16) | (uint32_t)__half_as_ushort(la);
}
__device__ __forceinline__ uint32_t f16_pack2(float a, float b) {
    __half ha = __float2half_rn(a), hb = __float2half_rn(b);
    return ((uint32_t)__half_as_ushort(hb) << 16) | (uint32_t)__half_as_ushort(ha);
}
__device__ __forceinline__ void mma_f16(float* c, const uint32_t* a, const uint32_t* b) {
    asm volatile(
        "mma.sync.aligned.m16n8k16.row.col.f32.f16.f16.f32 "
        "{%0,%1,%2,%3}, {%4,%5,%6,%7}, {%8,%9}, {%0,%1,%2,%3};"
        : "+f"(c[0]), "+f"(c[1]), "+f"(c[2]), "+f"(c[3])
        : "r"(a[0]), "r"(a[1]), "r"(a[2]), "r"(a[3]), "r"(b[0]), "r"(b[1]));
}
__device__ __forceinline__ void cp16(uint32_t s, const void* g) {
    asm volatile("cp.async.cg.shared.global [%0], [%1], 16;" :: "r"(s), "l"(g));
}
__device__ __forceinline__ void cp_commit() { asm volatile("cp.async.commit_group;" ::: "memory"); }
template <int N> __device__ __forceinline__ void cp_wait() {
    asm volatile("cp.async.wait_group %0;" :: "n"(N) : "memory");
}

// ========== shared GEMM core: BK=32, 3-stage ring, paired-B planes =========
template <int PASSES>
__device__ __forceinline__ void gemm_core(
    uint32_t* smBase, uint32_t sb0,
    const uint32_t* __restrict__ AH, const uint32_t* __restrict__ AL, int nktA,
    const uint32_t* __restrict__ BH, const uint32_t* __restrict__ BL, int nktB,
    int mtBase, int pBase, int nk32, float (&acc)[4][8][4])
{
    constexpr bool P3 = (PASSES == 3);
    constexpr int OFF_ALO = 2048;
    constexpr int OFF_B  = P3 ? 4096 : 2048;
    constexpr int OFF_BLO = OFF_B + 2048;
    constexpr int STG = P3 ? 8192 : 4096;

    const int tid = threadIdx.x, wid = tid >> 5, lane = tid & 31;
    const int warpM = wid & 1, warpN = wid >> 1;

    const uint32_t *pA[4], *pAl[4], *pB[4], *pBl[4];
    uint32_t dOff[4];
#pragma unroll
    for (int j = 0; j < 4; j++) {
        const int gi = tid + j * 128;
        const int ks = gi >> 8;
        const int blk = (gi >> 5) & 7;
        const int w = (gi & 31) * 4;
        dOff[j] = (uint32_t)(ks * 1024 + blk * 128 + w);
        pA[j] = AH + ((size_t)(mtBase + blk) * nktA + ks) * 128 + w;
        pB[j] = BH + ((size_t)(pBase + blk) * nktB + ks) * 128 + w;
        if (P3) {
            pAl[j] = AL + ((size_t)(mtBase + blk) * nktA + ks) * 128 + w;
            pBl[j] = BL + ((size_t)(pBase + blk) * nktB + ks) * 128 + w;
        }
    }

    auto issue = [&](int it, int stg) {
        const uint32_t s = sb0 + stg * (STG * 4);
        const size_t kadd = (size_t)it * 256;
#pragma unroll
        for (int j = 0; j < 4; j++) {
            cp16(s + dOff[j] * 4, pA[j] + kadd);
            if (P3) cp16(s + (OFF_ALO + dOff[j]) * 4, pAl[j] + kadd);
            cp16(s + (OFF_B + dOff[j]) * 4, pB[j] + kadd);
            if (P3) cp16(s + (OFF_BLO + dOff[j]) * 4, pBl[j] + kadd);
        }
        cp_commit();
    };

#pragma unroll
    for (int mt = 0; mt < 4; mt++)
#pragma unroll
        for (int nt = 0; nt < 8; nt++)
#pragma unroll
            for (int e = 0; e < 4; e++) acc[mt][nt][e] = 0.0f;

    __syncthreads();
    issue(0, 0);
    issue(1, 1);

    int slot = 0;
    for (int i = 0; i < nk32; i++) {
        if (i + 1 < nk32) cp_wait<1>();
        else              cp_wait<0>();
        __syncthreads();

        if (i + 2 < nk32) {
            int nslot = slot + 2;
            if (nslot >= 3) nslot -= 3;
            issue(i + 2, nslot);
        }

        const uint32_t* s = smBase + slot * STG;
#pragma unroll
        for (int ks = 0; ks < 2; ks++) {
            const uint32_t* sl = s + ks * 1024;
            uint32_t aHi[4][4], aLo[4][4], bHi[8][2], bLo[8][2];
#pragma unroll
            for (int mt = 0; mt < 4; mt++) {
                const uint32_t* ap = sl + (warpM * 4 + mt) * 128 + lane * 4;
                *(uint4*)aHi[mt] = *(const uint4*)ap;
                if (P3) *(uint4*)aLo[mt] = *(const uint4*)(ap + OFF_ALO);
            }
#pragma unroll
            for (int pp = 0; pp < 4; pp++) {
                const uint32_t* bp = sl + OFF_B + (warpN * 4 + pp) * 128 + lane * 4;
                const uint4 bh = *(const uint4*)bp;
                bHi[2 * pp][0] = bh.x; bHi[2 * pp][1] = bh.y;
                bHi[2 * pp + 1][0] = bh.z; bHi[2 * pp + 1][1] = bh.w;
                if (P3) {
                    const uint4 bl = *(const uint4*)(bp + 2048);
                    bLo[2 * pp][0] = bl.x; bLo[2 * pp][1] = bl.y;
                    bLo[2 * pp + 1][0] = bl.z; bLo[2 * pp + 1][1] = bl.w;
                }
            }
#pragma unroll
            for (int mt = 0; mt < 4; mt++)
#pragma unroll
                for (int nt = 0; nt < 8; nt++)
                    mma_f16(acc[mt][nt], aHi[mt], bHi[nt]);
            if (P3) {
#pragma unroll
                for (int mt = 0; mt < 4; mt++)
#pragma unroll
                    for (int nt = 0; nt < 8; nt++)
                        mma_f16(acc[mt][nt], aHi[mt], bLo[nt]);
#pragma unroll
                for (int mt = 0; mt < 4; mt++)
#pragma unroll
                    for (int nt = 0; nt < 8; nt++)
                        mma_f16(acc[mt][nt], aLo[mt], bHi[nt]);
            }
        }

        if (++slot == 3) slot = 0;
    }
}

// ====== persistent Q+K+V projection (merged queue: 1536 tiles) =============
__global__ void __launch_bounds__(128, 2) gemm_qkv(
    const uint32_t* __restrict__ qAH, const uint32_t* __restrict__ qAL,
    const uint32_t* __restrict__ WqH, const uint32_t* __restrict__ WqL,
    const float* __restrict__ bq,
    uint32_t* __restrict__ QH, uint32_t* __restrict__ QL,
    const uint32_t* __restrict__ kAH, const uint32_t* __restrict__ kAL,
    const uint32_t* __restrict__ WkH, const uint32_t* __restrict__ WkL,
    const float* __restrict__ bk,
    uint32_t* __restrict__ KH, uint32_t* __restrict__ KL,
    const uint32_t* __restrict__ vAH, const uint32_t* __restrict__ WvH,
    const float* __restrict__ bv, uint32_t* __restrict__ Vh)
{
    extern __shared__ uint32_t sm[];
    const uint32_t sb0 = (uint32_t)__cvta_generic_to_shared(sm);
    const int lane = threadIdx.x & 31, wid = threadIdx.x >> 5;
    const int warpM = wid & 1, warpN = wid >> 1;
    const int gID = lane >> 2, tig = lane & 3;

    for (int t = blockIdx.x; t < 1536; t += gridDim.x) {
        if (t < 1024) {
            const int bx = t & 7, by = (t >> 3) & 63, z = t >> 9;
            const int rowBase = by * 128, colBase = bx * 128;
            const uint32_t* AH = z ? kAH : qAH;
            const uint32_t* AL = z ? kAL : qAL;
            const uint32_t* BH = z ? WkH : WqH;
            const uint32_t* BL = z ? WkL : WqL;
            const float* bias = z ? bk : bq;

            float acc[4][8][4];
            gemm_core<3>(sm, sb0, AH, AL, 64, BH, BL, 64, by * 8, bx * 8, 32, acc);

#pragma unroll
            for (int mt = 0; mt < 4; mt++) {
                const int r = rowBase + warpM * 64 + mt * 16 + gID;
#pragma unroll
                for (int nt = 0; nt < 8; nt++) {
                    const int c = colBase + warpN * 64 + nt * 8 + tig * 2;
                    const float b0 = bias[c], b1 = bias[c + 1];
                    const float v00 = acc[mt][nt][0] + b0, v01 = acc[mt][nt][1] + b1;
                    const float v10 = acc[mt][nt][2] + b0, v11 = acc[mt][nt][3] + b1;
                    const int kp = (c & 15) >> 1;
                    uint32_t h0, l0, h1, l1;
                    f16_split2(v00, v01, h0, l0);
                    f16_split2(v10, v11, h1, l1);
                    if (z == 0) {
                        const int lfr = ((r & 7) << 2) | (kp & 3);
                        const int rg0 = (kp >> 2) << 1;
                        const size_t tb = ((size_t)(r >> 4) * 64 + (c >> 4)) * 128 + lfr * 4 + rg0;
                        uint2 uh = {h0, h1}, ul = {l0, l1};
                        *(uint2*)(QH + tb) = uh;
                        *(uint2*)(QL + tb) = ul;
                    } else {
                        const int lfr = ((r & 7) << 2) | (kp & 3);
                        const int rg = kp >> 2;
                        const size_t tb = ((size_t)(r >> 4) * 64 + (c >> 4)) * 128 + lfr * 4 + rg;
                        KH[tb] = h0; KH[tb + 2] = h1;
                        KL[tb] = l0; KL[tb + 2] = l1;
                    }
                }
            }
        } else {
            const int tv = t - 1024;
            const int bx = tv & 7, by = tv >> 3;
            const int rowBase = by * 128, colBase = bx * 128;

            float acc[4][8][4];
            gemm_core<1>(sm, sb0, vAH, nullptr, 64, WvH, nullptr, 64, by * 8, bx * 8, 32, acc);

#pragma unroll
            for (int mt = 0; mt < 4; mt++) {
                const int r = rowBase + warpM * 64 + mt * 16 + gID;
#pragma unroll
                for (int nt = 0; nt < 8; nt++) {
                    const int c = colBase + warpN * 64 + nt * 8 + tig * 2;
                    const float b0 = bv[c], b1 = bv[c + 1];
                    Vh[(size_t)r * (MODEL / 2) + (c >> 1)] = f16_pack2(acc[mt][nt][0] + b0, acc[mt][nt][1] + b1);
                    Vh[(size_t)(r + 8) * (MODEL / 2) + (c >> 1)] = f16_pack2(acc[mt][nt][2] + b0, acc[mt][nt][3] + b1);
                }
            }
        }
    }
}

// ============== persistent scores (3-pass) =================================
__global__ void __launch_bounds__(128, 2) gemm_s(
    const uint32_t* __restrict__ QH, const uint32_t* __restrict__ QL,
    const uint32_t* __restrict__ KH, const uint32_t* __restrict__ KL,
    float* __restrict__ S)
{
    extern __shared__ uint32_t sm[];
    const uint32_t sb0 = (uint32_t)__cvta_generic_to_shared(sm);
    const int lane = threadIdx.x & 31, wid = threadIdx.x >> 5;
    const int warpM = wid & 1, warpN = wid >> 1;
    const int gID = lane >> 2, tig = lane & 3;

    for (int t = blockIdx.x; t < 1024; t += gridDim.x) {
        const int bx = t & 15, by = (t >> 4) & 15, z = t >> 8;
        const int rowBase = by * 128, colBase = bx * 128;
        float* C = S + (size_t)z * SEQ * SEQ;

        float acc[4][8][4];
        gemm_core<3>(sm, sb0, QH, QL, 64, KH, KL, 64,
                     z * 128 + by * 8, z * 128 + bx * 8, 32, acc);

#pragma unroll
        for (int mt = 0; mt < 4; mt++) {
            const int r = rowBase + warpM * 64 + mt * 16 + gID;
#pragma unroll
            for (int nt = 0; nt < 8; nt++) {
                const int c = colBase + warpN * 64 + nt * 8 + tig * 2;
                float2 o0 = {acc[mt][nt][0] * 0.03125f, acc[mt][nt][1] * 0.03125f};
                float2 o1 = {acc[mt][nt][2] * 0.03125f, acc[mt][nt][3] * 0.03125f};
                *(float2*)(C + (size_t)r * SEQ + c) = o0;
                *(float2*)(C + (size_t)(r + 8) * SEQ + c) = o1;
            }
        }
    }
}

// ============== persistent PV (1-pass) =====================================
__global__ void __launch_bounds__(128, 2) gemm_pv(
    const uint32_t* __restrict__ P, const uint32_t* __restrict__ VT,
    float* __restrict__ O)
{
    extern __shared__ uint32_t sm[];
    const uint32_t sb0 = (uint32_t)__cvta_generic_to_shared(sm);
    const int lane = threadIdx.x & 31, wid = threadIdx.x >> 5;
    const int warpM = wid & 1, warpN = wid >> 1;
    const int gID = lane >> 2, tig = lane & 3;

    for (int t = blockIdx.x; t < 512; t += gridDim.x) {
        const int bx = t & 7, by = (t >> 3) & 15, z = t >> 7;
        const int rowBase = by * 128, colBase = bx * 128;
        float* C = O + (size_t)z * SEQ * MODEL;

        float acc[4][8][4];
        gemm_core<1>(sm, sb0, P, nullptr, SEQ / 16, VT, nullptr, SEQ / 16,
                     z * 128 + by * 8, z * 64 + bx * 8, 64, acc);

#pragma unroll
        for (int mt = 0; mt < 4; mt++) {
            const int r = rowBase + warpM * 64 + mt * 16 + gID;
#pragma unroll
            for (int nt = 0; nt < 8; nt++) {
                const int c = colBase + warpN * 64 + nt * 8 + tig * 2;
                float2 o0 = {acc[mt][nt][0], acc[mt][nt][1]};
                float2 o1 = {acc[mt][nt][2], acc[mt][nt][3]};
                *(float2*)(C + (size_t)r * MODEL + c) = o0;
                *(float2*)(C + (size_t)(r + 8) * MODEL + c) = o1;
            }
        }
    }
}

// ============ coalesced pre-split: X row-major -> A-frag planes ============
// Block = 16 rows x 128 cols; frag layout staged in smem; uint4 stores out.
__global__ void split_a3(const float* __restrict__ q, const float* __restrict__ k,
                         const float* __restrict__ v,
                         uint32_t* __restrict__ qAH, uint32_t* __restrict__ qAL,
                         uint32_t* __restrict__ kAH, uint32_t* __restrict__ kAL,
                         uint32_t* __restrict__ vAH) {
    __shared__ uint32_t sh[8][128];
    __shared__ uint32_t slo[8][128];
    const int z = blockIdx.z;
    const float* X = (z == 0) ? q : (z == 1) ? k : v;
    uint32_t* AH = (z == 0) ? qAH : (z == 1) ? kAH : vAH;
    uint32_t* AL = (z == 0) ? qAL : (z == 1) ? kAL : nullptr;
    const bool doLo = (z != 2);

    const int r0 = blockIdx.y * 16;
    const int c0 = blockIdx.x * 128;
    const int tid = threadIdx.x;

#pragma unroll
    for (int jj = 0; jj < 2; jj++) {
        const int f4 = tid + jj * 256;          // 0..511
        const int rr = f4 >> 5;                 // 0..15
        const int cc4 = f4 & 31;                // float4 within row
        const float4 vv = *(const float4*)(X + (size_t)(r0 + rr) * MODEL + c0 + cc4 * 4);
        const float fp[4] = {vv.x, vv.y, vv.z, vv.w};
#pragma unroll
        for (int pi = 0; pi < 2; pi++) {
            const int cp = cc4 * 2 + pi;        // pair index 0..63
            const int ktile = cp >> 3;
            const int kp = cp & 7;
            const int w = (((rr & 7) << 2) | (kp & 3)) * 4 + ((rr >> 3) & 1) + ((kp >> 2) << 1);
            if (doLo) {
                uint32_t hi, lo;
                f16_split2(fp[2 * pi], fp[2 * pi + 1], hi, lo);
                sh[ktile][w] = hi;
                slo[ktile][w] = lo;
            } else {
                sh[ktile][w] = f16_pack2(fp[2 * pi], fp[2 * pi + 1]);
            }
        }
    }
    __syncthreads();

    const size_t base = ((size_t)(r0 >> 4) * 64 + (c0 >> 4)) * 128;
    const int ti = tid >> 5, wg = (tid & 31) * 4;
    *(uint4*)(AH + base + (size_t)ti * 128 + wg) = *(uint4*)&sh[ti][wg];
    if (doLo)
        *(uint4*)(AL + base + (size_t)ti * 128 + wg) = *(uint4*)&slo[ti][wg];
}

// W -> paired B-frag planes of W^T
__global__ void split_b3(const float* __restrict__ Wq, const float* __restrict__ Wk,
                         const float* __restrict__ Wv,
                         uint32_t* __restrict__ WqH, uint32_t* __restrict__ WqL,
                         uint32_t* __restrict__ WkH, uint32_t* __restrict__ WkL,
                         uint32_t* __restrict__ WvH) {
    const int z = blockIdx.z;
    const float* W = (z == 0) ? Wq : (z == 1) ? Wk : Wv;
    uint32_t* BH = (z == 0) ? WqH : (z == 1) ? WkH : WvH;
    uint32_t* BL = (z == 0) ? WqL : (z == 1) ? WkL : nullptr;

    __shared__ float s[64][65];
    const int k0 = blockIdx.y * 64, n0 = blockIdx.x * 64;
#pragma unroll
    for (int i = 0; i < 16; i++) {
        const int e = threadIdx.x + i * 256;
        s[e >> 6][e & 63] = W[(size_t)(k0 + (e >> 6)) * MODEL + n0 + (e & 63)];
    }
    __syncthreads();
#pragma unroll
    for (int i = 0; i < 8; i++) {
        const int e = threadIdx.x + i * 256;
        const int n = e >> 5, kp = e & 31;
        const float a = s[kp * 2][n], b = s[kp * 2 + 1][n];
        const int nG = n0 + n;
        const int kp7 = kp & 7;
        const int lfr = ((nG & 7) << 2) | (kp7 & 3);
        const int sel = (nG >> 3) & 1;
        const int rg = kp7 >> 2;
        const size_t w = ((size_t)(nG >> 4) * (MODEL / 16) + (k0 >> 4) + (kp >> 3)) * 128
                         + lfr * 4 + sel * 2 + rg;
        if (BL) {
            uint32_t hi, lo;
            f16_split2(a, b, hi, lo);
            BH[w] = hi;
            BL[w] = lo;
        } else {
            BH[w] = f16_pack2(a, b);
        }
    }
}

// ============ fused softmax (sparse exp) + V -> VT paired tiles ============
__global__ void fused_sm_vt(const float* __restrict__ S, uint32_t* __restrict__ P,
                            const uint32_t* __restrict__ Vh, uint32_t* __restrict__ VT) {
    __shared__ float red[8];
    __shared__ uint32_t smv[64][36];

    if (blockIdx.x < MTOT) {
        const int s = blockIdx.x;
        const float* row = S + (size_t)s * SEQ;
        const int tid = threadIdx.x;

        float x[8];
#pragma unroll
        for (int j = 0; j < 4; j++) {
            float2 v = *(const float2*)(row + 2 * (tid + j * 256));
            x[2 * j] = v.x;
            x[2 * j + 1] = v.y;
        }
        float m = x[0];
#pragma unroll
        for (int i = 1; i < 8; i++) m = fmaxf(m, x[i]);
#pragma unroll
        for (int o = 16; o > 0; o >>= 1) m = fmaxf(m, __shfl_xor_sync(0xffffffffu, m, o));
        if ((tid & 31) == 0) red[tid >> 5] = m;
        __syncthreads();
        m = red[0];
#pragma unroll
        for (int i = 1; i < 8; i++) m = fmaxf(m, red[i]);
        __syncthreads();

        float e[8], ssum = 0.0f;
        bool live = false;
#pragma unroll
        for (int i = 0; i < 8; i++) live |= (x[i] - m > -17.5f);
        if (__any_sync(0xffffffffu, live)) {
#pragma unroll
            for (int i = 0; i < 8; i++) {
                const float d = x[i] - m;
                e[i] = (d > -17.5f) ? expf(d) : 0.0f;
                ssum += e[i];
            }
        } else {
#pragma unroll
            for (int i = 0; i < 8; i++) e[i] = 0.0f;
        }
#pragma unroll
        for (int o = 16; o > 0; o >>= 1) ssum += __shfl_xor_sync(0xffffffffu, ssum, o);
        if ((tid & 31) == 0) red[tid >> 5] = ssum;
        __syncthreads();
        ssum = 0.0f;
#pragma unroll
        for (int i = 0; i < 8; i++) ssum += red[i];
        const float inv = 1.0f / ssum;

        const int laneRow = (s & 7) << 2;
        const int regRow = (s >> 3) & 1;
        const size_t mtOff = (size_t)(s >> 4) * 128;
#pragma unroll
        for (int j = 0; j < 4; j++) {
            const int cp = tid + j * 256;
            const int pl = cp & 7, kt = cp >> 3;
            const int lfr = laneRow | (pl & 3);
            const int rg = regRow | ((pl >> 2) << 1);
            P[(mtOff + kt) * 128 + lfr * 4 + rg] = f16_pack2(e[2 * j] * inv, e[2 * j + 1] * inv);
        }
    } else {
        const int b = blockIdx.x - MTOT;
        const int z = b >> 9;
        const int t0 = ((b >> 4) & 31) * 64;
        const int d0 = (b & 15) * 64;
        const int tr = threadIdx.x >> 3, dq = threadIdx.x & 7;
#pragma unroll
        for (int i = 0; i < 2; i++) {
            const int t = tr + i * 32;
            *(uint4*)&smv[t][dq * 4] =
                *(const uint4*)(Vh + (size_t)(z * SEQ + t0 + t) * (MODEL / 2) + (d0 >> 1) + dq * 4);
        }
        __syncthreads();
#pragma unroll
        for (int i = 0; i < 8; i++) {
            const int idx = threadIdx.x + i * 256;
            const int tile = idx >> 6, within = idx & 63;
            const int lfr = within >> 1, rg = within & 1;
            const int ntl = tile >> 2, ktl = tile & 3;
            const int n = ntl * 8 + (lfr >> 2);
            const int p = (lfr & 3) | (rg << 2);
            const int k = ktl * 16 + p * 2;
            const uint32_t a = smv[k][n >> 1], bb = smv[k + 1][n >> 1];
            const uint32_t h0 = (n & 1) ? (a >> 16) : (a & 0xffffu);
            const uint32_t h1 = (n & 1) ? (bb >> 16) : (bb & 0xffffu);
            const int gtile = (d0 >> 3) + ntl;
            const size_t addr = ((size_t)(z * 64 + (gtile >> 1)) * (SEQ / 16)
                                 + (t0 >> 4) + ktl) * 128
                                + lfr * 4 + (gtile & 1) * 2 + rg;
            VT[addr] = h0 | (h1 << 16);
        }
    }
}

// ------------------------------- launcher ----------------------------------
extern "C" void kernel_launch(void* const* d_in, const int* in_sizes, int n_in,
                              void* d_out, int out_size) {
    const float* q  = (const float*)d_in[0];
    const float* k  = (const float*)d_in[1];
    const float* v  = (const float*)d_in[2];
    const float* Wq = (const float*)d_in[3];
    const float* Wk = (const float*)d_in[4];
    const float* Wv = (const float*)d_in[5];
    const float* bq = (const float*)d_in[6];
    const float* bk = (const float*)d_in[7];
    const float* bv = (const float*)d_in[8];
    float* out = (float*)d_out;

    uint32_t *qAH, *qAL, *kAH, *kAL, *vAH;
    uint32_t *WqH, *WqL, *WkH, *WkL, *WvH;
    uint32_t *QH, *QL, *KH, *KL, *Vh, *VT, *P;
    float* Sp;
    cudaGetSymbolAddress((void**)&qAH, g_qAH);
    cudaGetSymbolAddress((void**)&qAL, g_qAL);
    cudaGetSymbolAddress((void**)&kAH, g_kAH);
    cudaGetSymbolAddress((void**)&kAL, g_kAL);
    cudaGetSymbolAddress((void**)&vAH, g_vAH);
    cudaGetSymbolAddress((void**)&WqH, g_WqH);
    cudaGetSymbolAddress((void**)&WqL, g_WqL);
    cudaGetSymbolAddress((void**)&WkH, g_WkH);
    cudaGetSymbolAddress((void**)&WkL, g_WkL);
    cudaGetSymbolAddress((void**)&WvH, g_WvH);
    cudaGetSymbolAddress((void**)&QH, g_QH);
    cudaGetSymbolAddress((void**)&QL, g_QL);
    cudaGetSymbolAddress((void**)&KH, g_KH);
    cudaGetSymbolAddress((void**)&KL, g_KL);
    cudaGetSymbolAddress((void**)&Vh, g_Vh);
    cudaGetSymbolAddress((void**)&VT, g_VT);
    cudaGetSymbolAddress((void**)&P,  g_P);
    cudaGetSymbolAddress((void**)&Sp, g_S);

    static int smem_set = 0;
    if (!smem_set) {
        cudaFuncSetAttribute(gemm_qkv, cudaFuncAttributeMaxDynamicSharedMemorySize, 98304);
        cudaFuncSetAttribute(gemm_s,   cudaFuncAttributeMaxDynamicSharedMemorySize, 98304);
        smem_set = 1;
    }

    split_a3<<<dim3(8, 512, 3), 256>>>(q, k, v, qAH, qAL, kAH, kAL, vAH);
    split_b3<<<dim3(16, 16, 3), 256>>>(Wq, Wk, Wv, WqH, WqL, WkH, WkL, WvH);

    gemm_qkv<<<PERSIST, 128, 98304>>>(qAH, qAL, WqH, WqL, bq, QH, QL,
                                      kAH, kAL, WkH, WkL, bk, KH, KL,
                                      vAH, WvH, bv, Vh);

    gemm_s<<<PERSIST, 128, 98304>>>(QH, QL, KH, KL, Sp);

    fused_sm_vt<<<MTOT + 2048, 256>>>(Sp, P, Vh, VT);

    gemm_pv<<<PERSIST, 128, 49152>>>(P, VT, out);
}